// round 15
// baseline (speedup 1.0000x reference)
#include <cuda_runtime.h>
#include <cuda_bf16.h>
#include <cstdint>
#include <cstddef>

#define VOCAB  32000
#define HIDDEN 1024
#define BATCH  8
#define SEQ    512
#define G4     (4*HIDDEN)       // 4096
#define MROWS  (BATCH*SEQ)      // 4096
#define LP_BLOCKS 128

// ---------------- static device scratch (no allocs allowed) ----------------
__device__ float g_xg [(size_t)MROWS * G4];              // [m][4H]
__device__ float g_hs [(size_t)MROWS * HIDDEN];          // [m][h]
__device__ float g_WhT[(size_t)G4 * HIDDEN];             // [col][k] fp32
__device__ float g_h  [2 * BATCH * HIDDEN];              // double-buffered h
__device__ int   g_ids[MROWS];
__device__ unsigned g_bar;                               // persistent-grid barrier
// bf16 split operands
__device__ __nv_bfloat16 g_hs_hi[(size_t)MROWS * HIDDEN];   // [m][k]
__device__ __nv_bfloat16 g_hs_lo[(size_t)MROWS * HIDDEN];
__device__ __nv_bfloat16 g_WT_hi[(size_t)VOCAB * HIDDEN];   // [v][k]
__device__ __nv_bfloat16 g_WT_lo[(size_t)VOCAB * HIDDEN];
__device__ __nv_bfloat16 g_WxT_hi[(size_t)G4 * HIDDEN];     // [n][k]
__device__ __nv_bfloat16 g_WxT_lo[(size_t)G4 * HIDDEN];
__device__ __nv_bfloat16 g_Wp_hi[(size_t)G4 * HIDDEN];      // permuted Wh rows, bf16
__device__ __nv_bfloat16 g_Wp_lo[(size_t)G4 * HIDDEN];

// ================= helpers =================
#define CP_ASYNC16(dst, src) \
    asm volatile("cp.async.cg.shared.global [%0], [%1], 16;" :: "r"(dst), "l"(src))
#define CP_COMMIT() asm volatile("cp.async.commit_group;" ::: "memory")
#define CP_WAIT(n)  asm volatile("cp.async.wait_group %0;" :: "n"(n) : "memory")

__device__ __forceinline__ uint32_t smem_u32(const void* p) {
    uint32_t a;
    asm("{ .reg .u64 t; cvta.to.shared.u64 t, %1; cvt.u32.u64 %0, t; }" : "=r"(a) : "l"(p));
    return a;
}
__device__ __forceinline__ void ldmx4(uint32_t* r, uint32_t addr) {
    asm volatile("ldmatrix.sync.aligned.m8n8.x4.shared.b16 {%0,%1,%2,%3}, [%4];"
                 : "=r"(r[0]), "=r"(r[1]), "=r"(r[2]), "=r"(r[3]) : "r"(addr));
}
__device__ __forceinline__ void mma16816(float* c, const uint32_t* a, const uint32_t* b) {
    asm volatile("mma.sync.aligned.m16n8k16.row.col.f32.bf16.bf16.f32 "
                 "{%0,%1,%2,%3}, {%4,%5,%6,%7}, {%8,%9}, {%0,%1,%2,%3};"
                 : "+f"(c[0]), "+f"(c[1]), "+f"(c[2]), "+f"(c[3])
                 : "r"(a[0]), "r"(a[1]), "r"(a[2]), "r"(a[3]), "r"(b[0]), "r"(b[1]));
}
__device__ __forceinline__ void bar_arrive() {
    unsigned dummy;
    asm volatile("atom.add.release.gpu.u32 %0, [%1], 1;"
                 : "=r"(dummy) : "l"(&g_bar) : "memory");
}
__device__ __forceinline__ unsigned bar_peek() {
    unsigned v;
    asm volatile("ld.acquire.gpu.u32 %0, [%1];" : "=r"(v) : "l"(&g_bar) : "memory");
    return v;
}

// ---------------- init: zero h, barrier ----------------
__global__ void init_state_kernel() {
    int i = blockIdx.x * 256 + threadIdx.x;
    if (i < 2 * BATCH * HIDDEN) g_h[i] = 0.f;
    if (i == 0)                 g_bar = 0u;
}

// ---------------- dtype-agnostic id decode ----------------
__global__ void decode_ids_kernel(const int* __restrict__ raw) {
    __shared__ int is64;
    if (threadIdx.x == 0) {
        int allzero = 1;
        for (int i = 0; i < 128; ++i)
            if (raw[2 * i + 1] != 0) { allzero = 0; break; }
        is64 = allzero;
    }
    __syncthreads();
    int i = blockIdx.x * 256 + threadIdx.x;
    if (i < MROWS) {
        int v = is64 ? raw[2 * i] : raw[i];
        if (v < 0) v = 0;
        if (v >= VOCAB) v = VOCAB - 1;
        g_ids[i] = v;
    }
}

// ---------------- transpose + split: W[k][n] -> dst_{hi,lo}[n][k] bf16 ----------------
__global__ void transpose_split_kernel(const float* __restrict__ W,
                                       __nv_bfloat16* __restrict__ dhi,
                                       __nv_bfloat16* __restrict__ dlo,
                                       int ncols) {
    __shared__ float t[32][33];
    int v0 = blockIdx.x * 32, k0 = blockIdx.y * 32;
    int x = threadIdx.x, y = threadIdx.y;
#pragma unroll
    for (int i = 0; i < 4; ++i)
        t[y + i * 8][x] = W[(size_t)(k0 + y + i * 8) * ncols + v0 + x];
    __syncthreads();
#pragma unroll
    for (int i = 0; i < 4; ++i) {
        float val = t[x][y + i * 8];
        __nv_bfloat16 hi = __float2bfloat16(val);
        size_t o = (size_t)(v0 + y + i * 8) * HIDDEN + k0 + x;
        dhi[o] = hi;
        dlo[o] = __float2bfloat16(val - __bfloat162float(hi));
    }
}

// ---------------- bf16 embedding gather ----------------
__global__ void gather_emb_bf16_kernel() {
    int m = blockIdx.x;
    int id = g_ids[(m & 7) * SEQ + (m >> 3)];
    const uint4* sh = (const uint4*)(g_WT_hi + (size_t)id * HIDDEN);
    const uint4* sl = (const uint4*)(g_WT_lo + (size_t)id * HIDDEN);
    uint4* dh = (uint4*)(g_hs_hi + (size_t)m * HIDDEN);
    uint4* dl = (uint4*)(g_hs_lo + (size_t)m * HIDDEN);
    dh[threadIdx.x] = sh[threadIdx.x];
    dl[threadIdx.x] = sl[threadIdx.x];
}

// ---------------- split hs -> bf16 hi/lo ----------------
__global__ void split_hs_kernel() {
    int i = (blockIdx.x * 256 + threadIdx.x) * 4;
    float4 v = *(const float4*)&g_hs[i];
    float vv[4] = {v.x, v.y, v.z, v.w};
#pragma unroll
    for (int j = 0; j < 4; ++j) {
        __nv_bfloat16 hi = __float2bfloat16(vv[j]);
        g_hs_hi[i + j] = hi;
        g_hs_lo[i + j] = __float2bfloat16(vv[j] - __bfloat162float(hi));
    }
}

// ---------------- Wh transpose (fp32) ----------------
__global__ void transpose_wh_kernel(const float* __restrict__ Wh) {
    __shared__ float t[32][33];
    int bx = blockIdx.x, by = blockIdx.y;
    int x = threadIdx.x, y = threadIdx.y;
#pragma unroll
    for (int i = 0; i < 4; ++i)
        t[y + i * 8][x] = Wh[(size_t)(bx * 32 + y + i * 8) * G4 + by * 32 + x];
    __syncthreads();
#pragma unroll
    for (int i = 0; i < 4; ++i)
        g_WhT[(size_t)(by * 32 + y + i * 8) * HIDDEN + bx * 32 + x] = t[x][y + i * 8];
}

// ---------------- permute + split Wh rows: row r = bx*32 + g*8 + jl ----------------
__global__ void wperm_split_kernel() {
    int r = blockIdx.x;
    int g = (r >> 3) & 3, jl = r & 7, bx = r >> 5;
    int c = g * HIDDEN + bx * 8 + jl;
    const float* src = g_WhT + (size_t)c * HIDDEN;
    int k = threadIdx.x * 8;
#pragma unroll
    for (int q = 0; q < 2; ++q) {
        float4 v = *(const float4*)(src + k + q * 4);
        float vv[4] = {v.x, v.y, v.z, v.w};
#pragma unroll
        for (int j = 0; j < 4; ++j) {
            __nv_bfloat16 hi = __float2bfloat16(vv[j]);
            g_Wp_hi[(size_t)r * HIDDEN + k + q * 4 + j] = hi;
            g_Wp_lo[(size_t)r * HIDDEN + k + q * 4 + j] =
                __float2bfloat16(vv[j] - __bfloat162float(hi));
        }
    }
}

// ================= persistent LSTM recurrence — HMMA gates GEMM =================
// 128 blocks x 256 threads (8 warps), 1 CTA/SM. Block owns permuted rows
// [bx*32, bx*32+32) = cols {g*1024 + bx*8 + jl}. Weight A-fragments (bf16 hi/lo)
// live in REGISTERS for all 512 steps. Warp w reduces k in [w*128, w*128+128).
// h split to bf16 hi/lo in smem each step; 3 products, fp32 accum.
// smem bytes: wstage 132096 | h_hi 16512 | h_lo 16512 | part 9216 | gsum 1024
#define LPW_STRIDE 2064                  // bytes per weight/h smem row (1032 bf16)
#define LP_OFF_WST 0
#define LP_OFF_HHI 132096
#define LP_OFF_HLO 148608
#define LP_OFF_PART 165120
#define LP_OFF_GSUM 174336
#define LP_SMEM_BYTES 175360

__global__ __launch_bounds__(256, 1) void lstm_persistent_kernel() {
    extern __shared__ char sm[];
    const uint32_t sbase = smem_u32(sm);
    float* part = (float*)(sm + LP_OFF_PART);   // [w][r(32)][9]
    float* gsum = (float*)(sm + LP_OFF_GSUM);   // [r*8+b]

    const int tid  = threadIdx.x;
    const int lane = tid & 31;
    const int w    = tid >> 5;                  // warp = k-slice
    const int bx   = blockIdx.x;

    // ---- stage permuted weight rows (32 x 1024 bf16, hi+lo) into smem ----
    {
        const uint4* srcH = (const uint4*)(g_Wp_hi + (size_t)bx * 32 * HIDDEN);
        const uint4* srcL = (const uint4*)(g_Wp_lo + (size_t)bx * 32 * HIDDEN);
        for (int q = tid; q < 32 * 128; q += 256) {
            int rl = q >> 7, qq = q & 127;
            *(uint4*)(sm + LP_OFF_WST + rl * LPW_STRIDE + qq * 16) = srcH[q];
            *(uint4*)(sm + LP_OFF_WST + 66048 + rl * LPW_STRIDE + qq * 16) = srcL[q];
        }
    }
    __syncthreads();

    // ---- load weight A-fragments into registers (2 j-tiles x 8 k16 x hi/lo) ----
    uint32_t wAhi[2][8][4], wAlo[2][8][4];
#pragma unroll
    for (int jt = 0; jt < 2; ++jt)
#pragma unroll
        for (int k16 = 0; k16 < 8; ++k16) {
            uint32_t off = (jt * 16 + (lane & 15)) * LPW_STRIDE
                         + (w * 128 + k16 * 16) * 2 + (lane >> 4) * 16;
            ldmx4(wAhi[jt][k16], sbase + LP_OFF_WST + off);
            ldmx4(wAlo[jt][k16], sbase + LP_OFF_WST + 66048 + off);
        }
    __syncthreads();

    // per-thread mappings
    const int rr = tid >> 3, rb = tid & 7;                     // reduce: row r, batch b
    const int xg_col = (rr >> 3) * HIDDEN + bx * 8 + (rr & 7);
    float c_reg = 0.f;
    const int jl3 = tid >> 3, b3 = tid & 7;                    // finalize (tid<64)

    // B-fragment load offsets (bytes): n = lane>>2, k pair = (lane&3)*2
    const uint32_t boff0 = (lane >> 2) * LPW_STRIDE + ((lane & 3) * 2) * 2;
    const uint32_t boff1 = boff0 + 16;                          // +8 k

    for (int t = 0; t < SEQ; ++t) {
        float xg_val = __ldg(&g_xg[((size_t)t * 8 + rb) * G4 + xg_col]);

        // ---- copy + split h: thread owns n = tid>>5, k block (tid&31)*32 ----
        {
            const float* hin = g_h + (t & 1) * (BATCH * HIDDEN);
            const int n = tid >> 5, k0t = (tid & 31) * 32;
            const float* src = hin + n * HIDDEN + k0t;
            char* dhi = sm + LP_OFF_HHI + n * LPW_STRIDE + k0t * 2;
            char* dlo = sm + LP_OFF_HLO + n * LPW_STRIDE + k0t * 2;
#pragma unroll
            for (int q = 0; q < 8; ++q) {
                float4 v = __ldcg((const float4*)(src + q * 4));
                __nv_bfloat162 h0 = __floats2bfloat162_rn(v.x, v.y);
                __nv_bfloat162 h1 = __floats2bfloat162_rn(v.z, v.w);
                __nv_bfloat162 l0 = __floats2bfloat162_rn(
                    v.x - __bfloat162float(__low2bfloat16(h0)),
                    v.y - __bfloat162float(__high2bfloat16(h0)));
                __nv_bfloat162 l1 = __floats2bfloat162_rn(
                    v.z - __bfloat162float(__low2bfloat16(h1)),
                    v.w - __bfloat162float(__high2bfloat16(h1)));
                *(uint32_t*)(dhi + q * 8)     = *(uint32_t*)&h0;
                *(uint32_t*)(dhi + q * 8 + 4) = *(uint32_t*)&h1;
                *(uint32_t*)(dlo + q * 8)     = *(uint32_t*)&l0;
                *(uint32_t*)(dlo + q * 8 + 4) = *(uint32_t*)&l1;
            }
        }
        __syncthreads();

        // ---- gates GEMM: 48 HMMA per warp ----
        float acc[2][4];
#pragma unroll
        for (int jt = 0; jt < 2; ++jt)
#pragma unroll
            for (int i = 0; i < 4; ++i) acc[jt][i] = 0.f;

        const uint32_t hibase = sbase + LP_OFF_HHI + w * 256;   // w*128 k * 2B
        const uint32_t lobase = sbase + LP_OFF_HLO + w * 256;
#pragma unroll
        for (int k16 = 0; k16 < 8; ++k16) {
            uint32_t bhi[2], blo[2];
            bhi[0] = *(const uint32_t*)(sm + (hibase - sbase) + k16 * 32 + boff0);
            bhi[1] = *(const uint32_t*)(sm + (hibase - sbase) + k16 * 32 + boff1);
            blo[0] = *(const uint32_t*)(sm + (lobase - sbase) + k16 * 32 + boff0);
            blo[1] = *(const uint32_t*)(sm + (lobase - sbase) + k16 * 32 + boff1);
#pragma unroll
            for (int jt = 0; jt < 2; ++jt) {
                mma16816(acc[jt], wAhi[jt][k16], bhi);   // Whi * hhi
                mma16816(acc[jt], wAhi[jt][k16], blo);   // Whi * hlo
                mma16816(acc[jt], wAlo[jt][k16], bhi);   // Wlo * hhi
            }
        }

        // ---- partials to smem: C frag rows lane>>2 / +8, cols (lane&3)*2 +{0,1} ----
        {
            const int crow = lane >> 2, cn = (lane & 3) * 2;
            float* pw = part + w * 288;
#pragma unroll
            for (int jt = 0; jt < 2; ++jt) {
                pw[(jt * 16 + crow) * 9 + cn]         = acc[jt][0];
                pw[(jt * 16 + crow) * 9 + cn + 1]     = acc[jt][1];
                pw[(jt * 16 + crow + 8) * 9 + cn]     = acc[jt][2];
                pw[(jt * 16 + crow + 8) * 9 + cn + 1] = acc[jt][3];
            }
        }
        __syncthreads();

        // ---- reduce over 8 warps ----
        {
            float s = 0.f;
#pragma unroll
            for (int ww = 0; ww < 8; ++ww) s += part[ww * 288 + rr * 9 + rb];
            gsum[tid] = s + xg_val;
        }
        __syncthreads();

        // ---- finalize: tid<64 -> (jl3, b3) ----
        if (tid < 64) {
            float gv0 = gsum[(0 * 8 + jl3) * 8 + b3];
            float gv1 = gsum[(1 * 8 + jl3) * 8 + b3];
            float gv2 = gsum[(2 * 8 + jl3) * 8 + b3];
            float gv3 = gsum[(3 * 8 + jl3) * 8 + b3];
            float i_ = 1.f / (1.f + expf(-gv0));
            float f_ = 1.f / (1.f + expf(-gv1));
            float gg = tanhf(gv2);
            float o_ = 1.f / (1.f + expf(-gv3));
            c_reg = f_ * c_reg + i_ * gg;
            float hn = o_ * tanhf(c_reg);
            int j = bx * 8 + jl3;
            g_h[((t + 1) & 1) * (BATCH * HIDDEN) + b3 * HIDDEN + j] = hn;
            g_hs[((size_t)t * 8 + b3) * HIDDEN + j] = hn;
        }
        __syncthreads();
        if (tid == 0) {
            bar_arrive();
            const unsigned target = (unsigned)LP_BLOCKS * (unsigned)(t + 1);
            while (bar_peek() < target) __nanosleep(32);
        }
        __syncthreads();
    }
}

// ================= fused 3-product bf16-split HMMA GEMM =================
#define L_STRIDE  80
#define L_AB      (128 * L_STRIDE)
#define L_STAGE   (4 * L_AB)               // Ahi|Alo|Bhi|Blo = 40960 B
#define L_SMEM    (2 * L_STAGE)            // 81920 B

template <int PERM>
__global__ __launch_bounds__(256, 2) void mma_gemm_kernel(
        const __nv_bfloat16* __restrict__ Ahi, const __nv_bfloat16* __restrict__ Alo,
        const __nv_bfloat16* __restrict__ Bhi, const __nv_bfloat16* __restrict__ Blo,
        const float* __restrict__ bias, float* __restrict__ out, int Ntot) {
    extern __shared__ char lsm[];
    const uint32_t sbase = smem_u32(lsm);

    const int tid  = threadIdx.x;
    const int lane = tid & 31;
    const int wid  = tid >> 5;
    const int wm   = wid >> 2;
    const int wn   = wid & 3;
    const int m0   = blockIdx.x * 128;
    const int n0   = blockIdx.y * 128;

    const int lrow = tid >> 2;
    const int lch  = tid & 3;

    float acc[4][4][4];
#pragma unroll
    for (int i = 0; i < 4; ++i)
#pragma unroll
        for (int j = 0; j < 4; ++j)
#pragma unroll
            for (int k = 0; k < 4; ++k) acc[i][j][k] = 0.f;

    auto load_chunk = [&](int c, int s) {
        const int k0 = c * 32;
        uint32_t sb0 = sbase + s * L_STAGE;
#pragma unroll
        for (int rr = 0; rr < 128; rr += 64) {
            const size_t aoff = (size_t)(m0 + lrow + rr) * HIDDEN + k0 + lch * 8;
            const size_t boff = (size_t)(n0 + lrow + rr) * HIDDEN + k0 + lch * 8;
            const uint32_t doff = (lrow + rr) * L_STRIDE + lch * 16;
            CP_ASYNC16(sb0 + 0 * L_AB + doff, Ahi + aoff);
            CP_ASYNC16(sb0 + 1 * L_AB + doff, Alo + aoff);
            CP_ASYNC16(sb0 + 2 * L_AB + doff, Bhi + boff);
            CP_ASYNC16(sb0 + 3 * L_AB + doff, Blo + boff);
        }
        CP_COMMIT();
    };

    load_chunk(0, 0);

    for (int c = 0; c < 32; ++c) {
        if (c + 1 < 32) {
            load_chunk(c + 1, (c + 1) & 1);
            CP_WAIT(1);
        } else {
            CP_WAIT(0);
        }
        __syncthreads();

        const uint32_t st = sbase + (c & 1) * L_STAGE;
#pragma unroll
        for (int k16 = 0; k16 < 2; ++k16) {
            const uint32_t koff = k16 * 32 + (lane >> 4) * 16;
            const uint32_t arow = (wm * 64 + (lane & 15)) * L_STRIDE + koff;
            const uint32_t brow = (wn * 32 + (lane & 15)) * L_STRIDE + koff;

            uint32_t a[4][4];
#pragma unroll
            for (int mf = 0; mf < 4; ++mf)
                ldmx4(a[mf], st + arow + mf * 16 * L_STRIDE);

            uint32_t bh[4][2], bl[4][2];
#pragma unroll
            for (int nh = 0; nh < 2; ++nh) {
                uint32_t t4[4];
                ldmx4(t4, st + 2 * L_AB + brow + nh * 16 * L_STRIDE);
                bh[nh * 2 + 0][0] = t4[0]; bh[nh * 2 + 0][1] = t4[2];
                bh[nh * 2 + 1][0] = t4[1]; bh[nh * 2 + 1][1] = t4[3];
                ldmx4(t4, st + 3 * L_AB + brow + nh * 16 * L_STRIDE);
                bl[nh * 2 + 0][0] = t4[0]; bl[nh * 2 + 0][1] = t4[2];
                bl[nh * 2 + 1][0] = t4[1]; bl[nh * 2 + 1][1] = t4[3];
            }

#pragma unroll
            for (int mf = 0; mf < 4; ++mf)
#pragma unroll
                for (int nf = 0; nf < 4; ++nf) {
                    mma16816(acc[mf][nf], a[mf], bh[nf]);
                    mma16816(acc[mf][nf], a[mf], bl[nf]);
                }

#pragma unroll
            for (int mf = 0; mf < 4; ++mf)
                ldmx4(a[mf], st + 1 * L_AB + arow + mf * 16 * L_STRIDE);
#pragma unroll
            for (int mf = 0; mf < 4; ++mf)
#pragma unroll
                for (int nf = 0; nf < 4; ++nf)
                    mma16816(acc[mf][nf], a[mf], bh[nf]);
        }
        __syncthreads();
    }

#pragma unroll
    for (int mf = 0; mf < 4; ++mf) {
        const int mbase = m0 + wm * 64 + mf * 16;
        const int m1 = mbase + (lane >> 2);
        const int m2 = m1 + 8;
        const size_t r1 = (PERM ? (size_t)((m1 & 7) * SEQ + (m1 >> 3)) : (size_t)m1) * Ntot;
        const size_t r2 = (PERM ? (size_t)((m2 & 7) * SEQ + (m2 >> 3)) : (size_t)m2) * Ntot;
#pragma unroll
        for (int nf = 0; nf < 4; ++nf) {
            const int n = n0 + wn * 32 + nf * 8 + (lane & 3) * 2;
            const float b0 = bias[n], b1 = bias[n + 1];
            float2 o1 = {acc[mf][nf][0] + b0, acc[mf][nf][1] + b1};
            float2 o2 = {acc[mf][nf][2] + b0, acc[mf][nf][3] + b1};
            *(float2*)(out + r1 + n) = o1;
            *(float2*)(out + r2 + n) = o2;
        }
    }
}

// ---------------- launch ----------------
extern "C" void kernel_launch(void* const* d_in, const int* in_sizes, int n_in,
                              void* d_out, int out_size) {
    const int*   ids_raw  = (const int*)d_in[0];
    const float* W_out    = (const float*)d_in[1];       // [H][V]
    const float* b_out    = (const float*)d_in[2];       // [V]
    const float* Wx       = (const float*)d_in[3];       // [H][4H]
    const float* Wh       = (const float*)d_in[4];       // [H][4H]
    const float* b_lstm   = (const float*)d_in[5];       // [4H]
    float* out            = (float*)d_out;               // [B][S][V]

    void *p_xg, *p_hshi, *p_hslo, *p_wthi, *p_wtlo, *p_wxhi, *p_wxlo;
    cudaGetSymbolAddress(&p_xg,   g_xg);
    cudaGetSymbolAddress(&p_hshi, g_hs_hi);
    cudaGetSymbolAddress(&p_hslo, g_hs_lo);
    cudaGetSymbolAddress(&p_wthi, g_WT_hi);
    cudaGetSymbolAddress(&p_wtlo, g_WT_lo);
    cudaGetSymbolAddress(&p_wxhi, g_WxT_hi);
    cudaGetSymbolAddress(&p_wxlo, g_WxT_lo);

    cudaFuncSetAttribute(lstm_persistent_kernel,
                         cudaFuncAttributeMaxDynamicSharedMemorySize, LP_SMEM_BYTES);
    cudaFuncSetAttribute(mma_gemm_kernel<0>,
                         cudaFuncAttributeMaxDynamicSharedMemorySize, L_SMEM);
    cudaFuncSetAttribute(mma_gemm_kernel<1>,
                         cudaFuncAttributeMaxDynamicSharedMemorySize, L_SMEM);

    // 0) init; decode ids; transpose Wh; permute+split Wh; split W_out/Wx
    init_state_kernel<<<(2 * BATCH * HIDDEN + 255) / 256, 256>>>();
    decode_ids_kernel<<<(MROWS + 255) / 256, 256>>>(ids_raw);
    {
        dim3 tg(HIDDEN / 32, G4 / 32);
        transpose_wh_kernel<<<tg, dim3(32, 8)>>>(Wh);
    }
    wperm_split_kernel<<<G4, 128>>>();
    transpose_split_kernel<<<dim3(VOCAB / 32, HIDDEN / 32), dim3(32, 8)>>>(
        W_out, (__nv_bfloat16*)p_wthi, (__nv_bfloat16*)p_wtlo, VOCAB);
    transpose_split_kernel<<<dim3(G4 / 32, HIDDEN / 32), dim3(32, 8)>>>(
        Wx, (__nv_bfloat16*)p_wxhi, (__nv_bfloat16*)p_wxlo, G4);

    // 1) bf16 embedding gather into g_hs_hi/lo
    gather_emb_bf16_kernel<<<MROWS, 128>>>();

    // 2) x_gates = emb @ Wx + b_lstm (fused 3-product HMMA)
    mma_gemm_kernel<0><<<dim3(MROWS / 128, G4 / 128), 256, L_SMEM>>>(
        (const __nv_bfloat16*)p_hshi, (const __nv_bfloat16*)p_hslo,
        (const __nv_bfloat16*)p_wxhi, (const __nv_bfloat16*)p_wxlo,
        b_lstm, (float*)p_xg, G4);

    // 3) recurrence: persistent HMMA kernel, 512 steps
    lstm_persistent_kernel<<<LP_BLOCKS, 256, LP_SMEM_BYTES>>>();

    // 4) split hs to bf16 hi/lo
    split_hs_kernel<<<(MROWS * HIDDEN / 4) / 256, 256>>>();

    // 5) logits = hs @ W_out + b_out (fused 3-product HMMA, (b,s) permute)
    mma_gemm_kernel<1><<<dim3(MROWS / 128, VOCAB / 128), 256, L_SMEM>>>(
        (const __nv_bfloat16*)p_hshi, (const __nv_bfloat16*)p_hslo,
        (const __nv_bfloat16*)p_wthi, (const __nv_bfloat16*)p_wtlo,
        b_out, out, VOCAB);
}

// round 16
// speedup vs baseline: 1.0966x; 1.0966x over previous
#include <cuda_runtime.h>
#include <cuda_bf16.h>
#include <cstdint>
#include <cstddef>

#define VOCAB  32000
#define HIDDEN 1024
#define BATCH  8
#define SEQ    512
#define G4     (4*HIDDEN)       // 4096
#define MROWS  (BATCH*SEQ)      // 4096
#define LP_BLOCKS 128

// ---------------- static device scratch (no allocs allowed) ----------------
__device__ float g_xg [(size_t)MROWS * G4];              // [m][4H]
__device__ float g_hs [(size_t)MROWS * HIDDEN];          // [m][h]
__device__ float g_WhT[(size_t)G4 * HIDDEN];             // [col][k] fp32
__device__ float g_h  [2 * BATCH * HIDDEN];              // double-buffered h
__device__ int   g_ids[MROWS];
__device__ unsigned g_bar;                               // persistent-grid barrier
// bf16 split operands (g_hs_hi/lo double as emb_hi/lo before the recurrence)
__device__ __nv_bfloat16 g_hs_hi[(size_t)MROWS * HIDDEN];   // [m][k]
__device__ __nv_bfloat16 g_hs_lo[(size_t)MROWS * HIDDEN];
__device__ __nv_bfloat16 g_WT_hi[(size_t)VOCAB * HIDDEN];   // [v][k]
__device__ __nv_bfloat16 g_WT_lo[(size_t)VOCAB * HIDDEN];
__device__ __nv_bfloat16 g_WxT_hi[(size_t)G4 * HIDDEN];     // [n][k]
__device__ __nv_bfloat16 g_WxT_lo[(size_t)G4 * HIDDEN];

// ================= helpers =================
#define CP_ASYNC16(dst, src) \
    asm volatile("cp.async.cg.shared.global [%0], [%1], 16;" :: "r"(dst), "l"(src))
#define CP_COMMIT() asm volatile("cp.async.commit_group;" ::: "memory")
#define CP_WAIT(n)  asm volatile("cp.async.wait_group %0;" :: "n"(n) : "memory")

__device__ __forceinline__ uint32_t smem_u32(const void* p) {
    uint32_t a;
    asm("{ .reg .u64 t; cvta.to.shared.u64 t, %1; cvt.u32.u64 %0, t; }" : "=r"(a) : "l"(p));
    return a;
}
__device__ __forceinline__ void ldmx4(uint32_t* r, uint32_t addr) {
    asm volatile("ldmatrix.sync.aligned.m8n8.x4.shared.b16 {%0,%1,%2,%3}, [%4];"
                 : "=r"(r[0]), "=r"(r[1]), "=r"(r[2]), "=r"(r[3]) : "r"(addr));
}
__device__ __forceinline__ void mma16816(float* c, const uint32_t* a, const uint32_t* b) {
    asm volatile("mma.sync.aligned.m16n8k16.row.col.f32.bf16.bf16.f32 "
                 "{%0,%1,%2,%3}, {%4,%5,%6,%7}, {%8,%9}, {%0,%1,%2,%3};"
                 : "+f"(c[0]), "+f"(c[1]), "+f"(c[2]), "+f"(c[3])
                 : "r"(a[0]), "r"(a[1]), "r"(a[2]), "r"(a[3]), "r"(b[0]), "r"(b[1]));
}
// packed dual-FMA: lanes (lo,hi) of b64 operands, acc += w * h elementwise
__device__ __forceinline__ void fma2(unsigned long long& acc,
                                     unsigned long long w2,
                                     unsigned long long h2) {
    asm("fma.rn.f32x2 %0, %1, %2, %0;" : "+l"(acc) : "l"(w2), "l"(h2));
}
__device__ __forceinline__ float pairsum(unsigned long long v) {
    float lo, hi;
    asm("mov.b64 {%0, %1}, %2;" : "=f"(lo), "=f"(hi) : "l"(v));
    return lo + hi;
}
__device__ __forceinline__ void bar_arrive() {
    unsigned dummy;
    asm volatile("atom.add.release.gpu.u32 %0, [%1], 1;"
                 : "=r"(dummy) : "l"(&g_bar) : "memory");
}
__device__ __forceinline__ unsigned bar_peek() {
    unsigned v;
    asm volatile("ld.acquire.gpu.u32 %0, [%1];" : "=r"(v) : "l"(&g_bar) : "memory");
    return v;
}

// ---------------- init: zero h, barrier ----------------
__global__ void init_state_kernel() {
    int i = blockIdx.x * 256 + threadIdx.x;
    if (i < 2 * BATCH * HIDDEN) g_h[i] = 0.f;
    if (i == 0)                 g_bar = 0u;
}

// ---------------- dtype-agnostic id decode ----------------
__global__ void decode_ids_kernel(const int* __restrict__ raw) {
    __shared__ int is64;
    if (threadIdx.x == 0) {
        int allzero = 1;
        for (int i = 0; i < 128; ++i)
            if (raw[2 * i + 1] != 0) { allzero = 0; break; }
        is64 = allzero;
    }
    __syncthreads();
    int i = blockIdx.x * 256 + threadIdx.x;
    if (i < MROWS) {
        int v = is64 ? raw[2 * i] : raw[i];
        if (v < 0) v = 0;
        if (v >= VOCAB) v = VOCAB - 1;
        g_ids[i] = v;
    }
}

// ---------------- transpose + split: W[k][n] -> dst_{hi,lo}[n][k] bf16 ----------------
__global__ void transpose_split_kernel(const float* __restrict__ W,
                                       __nv_bfloat16* __restrict__ dhi,
                                       __nv_bfloat16* __restrict__ dlo,
                                       int ncols) {
    __shared__ float t[32][33];
    int v0 = blockIdx.x * 32, k0 = blockIdx.y * 32;
    int x = threadIdx.x, y = threadIdx.y;
#pragma unroll
    for (int i = 0; i < 4; ++i)
        t[y + i * 8][x] = W[(size_t)(k0 + y + i * 8) * ncols + v0 + x];
    __syncthreads();
#pragma unroll
    for (int i = 0; i < 4; ++i) {
        float val = t[x][y + i * 8];
        __nv_bfloat16 hi = __float2bfloat16(val);
        size_t o = (size_t)(v0 + y + i * 8) * HIDDEN + k0 + x;
        dhi[o] = hi;
        dlo[o] = __float2bfloat16(val - __bfloat162float(hi));
    }
}

// ---------------- bf16 embedding gather ----------------
__global__ void gather_emb_bf16_kernel() {
    int m = blockIdx.x;
    int id = g_ids[(m & 7) * SEQ + (m >> 3)];
    const uint4* sh = (const uint4*)(g_WT_hi + (size_t)id * HIDDEN);
    const uint4* sl = (const uint4*)(g_WT_lo + (size_t)id * HIDDEN);
    uint4* dh = (uint4*)(g_hs_hi + (size_t)m * HIDDEN);
    uint4* dl = (uint4*)(g_hs_lo + (size_t)m * HIDDEN);
    dh[threadIdx.x] = sh[threadIdx.x];
    dl[threadIdx.x] = sl[threadIdx.x];
}

// ---------------- split hs -> bf16 hi/lo ----------------
__global__ void split_hs_kernel() {
    int i = (blockIdx.x * 256 + threadIdx.x) * 4;
    float4 v = *(const float4*)&g_hs[i];
    float vv[4] = {v.x, v.y, v.z, v.w};
#pragma unroll
    for (int j = 0; j < 4; ++j) {
        __nv_bfloat16 hi = __float2bfloat16(vv[j]);
        g_hs_hi[i + j] = hi;
        g_hs_lo[i + j] = __float2bfloat16(vv[j] - __bfloat162float(hi));
    }
}

// ---------------- Wh transpose (fp32) ----------------
__global__ void transpose_wh_kernel(const float* __restrict__ Wh) {
    __shared__ float t[32][33];
    int bx = blockIdx.x, by = blockIdx.y;
    int x = threadIdx.x, y = threadIdx.y;
#pragma unroll
    for (int i = 0; i < 4; ++i)
        t[y + i * 8][x] = Wh[(size_t)(bx * 32 + y + i * 8) * G4 + by * 32 + x];
    __syncthreads();
#pragma unroll
    for (int i = 0; i < 4; ++i)
        g_WhT[(size_t)(by * 32 + y + i * 8) * HIDDEN + bx * 32 + x] = t[x][y + i * 8];
}

// ================= persistent LSTM recurrence (FFMA2, register weights) ========
// 128 blocks x 256 threads. Warp = jl, lanes = contiguous float4 k-chunks.
// Wh weights in registers (as b64 k-pairs) for all 512 steps. Inner math uses
// fma.rn.f32x2: lanes carry (k, k+1) partial sums; merged at part-write time.
// Batches processed in halves of 4 to cap live accumulators at 32 regs.
#define LP_SMEM_BYTES ((8192 + 8448 + 256) * 4)
__global__ __launch_bounds__(256, 1) void lstm_persistent_kernel() {
    extern __shared__ float sm[];
    float* h_s  = sm;              // [b][k]      8 x 1024
    float* part = sm + 8192;       // [combo][33] 256 x 33
    float* gsum = sm + 16640;      // [256]

    const int tid = threadIdx.x;
    const int j0  = blockIdx.x * 8;
    const int wjl = tid >> 5;
    const int ln  = tid & 31;

    // weights as b64 k-pairs: wreg2[c][g] = {(w_k,w_k+1),(w_k+2,w_k+3)}
    ulonglong2 wreg2[8][4];
#pragma unroll
    for (int c = 0; c < 8; ++c)
#pragma unroll
        for (int g = 0; g < 4; ++g)
            wreg2[c][g] = *(const ulonglong2*)&g_WhT[
                (size_t)(g * HIDDEN + j0 + wjl) * HIDDEN + c * 128 + ln * 4];

    const int rjl = tid >> 5, rg = (tid >> 3) & 3, rb = tid & 7;
    const int xg_col = rg * HIDDEN + j0 + rjl;
    float c_reg = 0.f;
    const int jl3 = tid >> 3, b3 = tid & 7;

    __syncthreads();

    for (int t = 0; t < SEQ; ++t) {
        float xg_val = __ldg(&g_xg[((size_t)t * 8 + rb) * G4 + xg_col]);

        const float* hin = g_h + (t & 1) * (BATCH * HIDDEN);
        for (int i = tid * 4; i < BATCH * HIDDEN; i += 1024)
            *(float4*)&h_s[i] = __ldcg((const float4*)(hin + i));
        __syncthreads();

#pragma unroll
        for (int half = 0; half < 2; ++half) {
            unsigned long long acc2[4][4];
#pragma unroll
            for (int g = 0; g < 4; ++g)
#pragma unroll
                for (int b = 0; b < 4; ++b) acc2[g][b] = 0ull;

#pragma unroll
            for (int c = 0; c < 8; ++c) {
                const int k = c * 128 + ln * 4;
                const ulonglong2 w0 = wreg2[c][0];
                const ulonglong2 w1 = wreg2[c][1];
                const ulonglong2 w2 = wreg2[c][2];
                const ulonglong2 w3 = wreg2[c][3];
#pragma unroll
                for (int b = 0; b < 4; ++b) {
                    const int bb = half * 4 + b;
                    ulonglong2 hv = *(const ulonglong2*)&h_s[bb * 1024 + k];
                    fma2(acc2[0][b], w0.x, hv.x);
                    fma2(acc2[0][b], w0.y, hv.y);
                    fma2(acc2[1][b], w1.x, hv.x);
                    fma2(acc2[1][b], w1.y, hv.y);
                    fma2(acc2[2][b], w2.x, hv.x);
                    fma2(acc2[2][b], w2.y, hv.y);
                    fma2(acc2[3][b], w3.x, hv.x);
                    fma2(acc2[3][b], w3.y, hv.y);
                }
            }
#pragma unroll
            for (int g = 0; g < 4; ++g)
#pragma unroll
                for (int b = 0; b < 4; ++b)
                    part[((wjl * 4 + g) * 8 + half * 4 + b) * 33 + ln] =
                        pairsum(acc2[g][b]);
        }
        __syncthreads();

        {
            float s = 0.f;
            const float* pr = part + tid * 33;
#pragma unroll
            for (int i = 0; i < 32; ++i) s += pr[i];
            gsum[tid] = s + xg_val;
        }
        __syncthreads();

        if (tid < 64) {
            float gv0 = gsum[jl3 * 32 + 0 + b3];
            float gv1 = gsum[jl3 * 32 + 8 + b3];
            float gv2 = gsum[jl3 * 32 + 16 + b3];
            float gv3 = gsum[jl3 * 32 + 24 + b3];
            float i_ = 1.f / (1.f + expf(-gv0));
            float f_ = 1.f / (1.f + expf(-gv1));
            float gg = tanhf(gv2);
            float o_ = 1.f / (1.f + expf(-gv3));
            c_reg = f_ * c_reg + i_ * gg;
            float hn = o_ * tanhf(c_reg);
            int j = j0 + jl3;
            g_h[((t + 1) & 1) * (BATCH * HIDDEN) + b3 * HIDDEN + j] = hn;
            g_hs[((size_t)t * 8 + b3) * HIDDEN + j] = hn;
        }
        __syncthreads();
        if (tid == 0) {
            bar_arrive();
            const unsigned target = (unsigned)LP_BLOCKS * (unsigned)(t + 1);
            while (bar_peek() < target) __nanosleep(32);
        }
        __syncthreads();
    }
}

// ================= fused 3-product bf16-split HMMA GEMM =================
#define L_STRIDE  80
#define L_AB      (128 * L_STRIDE)
#define L_STAGE   (4 * L_AB)               // Ahi|Alo|Bhi|Blo = 40960 B
#define L_SMEM    (2 * L_STAGE)            // 81920 B

template <int PERM>
__global__ __launch_bounds__(256, 2) void mma_gemm_kernel(
        const __nv_bfloat16* __restrict__ Ahi, const __nv_bfloat16* __restrict__ Alo,
        const __nv_bfloat16* __restrict__ Bhi, const __nv_bfloat16* __restrict__ Blo,
        const float* __restrict__ bias, float* __restrict__ out, int Ntot) {
    extern __shared__ char lsm[];
    const uint32_t sbase = smem_u32(lsm);

    const int tid  = threadIdx.x;
    const int lane = tid & 31;
    const int wid  = tid >> 5;
    const int wm   = wid >> 2;
    const int wn   = wid & 3;
    const int m0   = blockIdx.x * 128;
    const int n0   = blockIdx.y * 128;

    const int lrow = tid >> 2;
    const int lch  = tid & 3;

    float acc[4][4][4];
#pragma unroll
    for (int i = 0; i < 4; ++i)
#pragma unroll
        for (int j = 0; j < 4; ++j)
#pragma unroll
            for (int k = 0; k < 4; ++k) acc[i][j][k] = 0.f;

    auto load_chunk = [&](int c, int s) {
        const int k0 = c * 32;
        uint32_t sb0 = sbase + s * L_STAGE;
#pragma unroll
        for (int rr = 0; rr < 128; rr += 64) {
            const size_t aoff = (size_t)(m0 + lrow + rr) * HIDDEN + k0 + lch * 8;
            const size_t boff = (size_t)(n0 + lrow + rr) * HIDDEN + k0 + lch * 8;
            const uint32_t doff = (lrow + rr) * L_STRIDE + lch * 16;
            CP_ASYNC16(sb0 + 0 * L_AB + doff, Ahi + aoff);
            CP_ASYNC16(sb0 + 1 * L_AB + doff, Alo + aoff);
            CP_ASYNC16(sb0 + 2 * L_AB + doff, Bhi + boff);
            CP_ASYNC16(sb0 + 3 * L_AB + doff, Blo + boff);
        }
        CP_COMMIT();
    };

    load_chunk(0, 0);

    for (int c = 0; c < 32; ++c) {
        if (c + 1 < 32) {
            load_chunk(c + 1, (c + 1) & 1);
            CP_WAIT(1);
        } else {
            CP_WAIT(0);
        }
        __syncthreads();

        const uint32_t st = sbase + (c & 1) * L_STAGE;
#pragma unroll
        for (int k16 = 0; k16 < 2; ++k16) {
            const uint32_t koff = k16 * 32 + (lane >> 4) * 16;
            const uint32_t arow = (wm * 64 + (lane & 15)) * L_STRIDE + koff;
            const uint32_t brow = (wn * 32 + (lane & 15)) * L_STRIDE + koff;

            uint32_t a[4][4];
#pragma unroll
            for (int mf = 0; mf < 4; ++mf)
                ldmx4(a[mf], st + arow + mf * 16 * L_STRIDE);

            uint32_t bh[4][2], bl[4][2];
#pragma unroll
            for (int nh = 0; nh < 2; ++nh) {
                uint32_t t4[4];
                ldmx4(t4, st + 2 * L_AB + brow + nh * 16 * L_STRIDE);
                bh[nh * 2 + 0][0] = t4[0]; bh[nh * 2 + 0][1] = t4[2];
                bh[nh * 2 + 1][0] = t4[1]; bh[nh * 2 + 1][1] = t4[3];
                ldmx4(t4, st + 3 * L_AB + brow + nh * 16 * L_STRIDE);
                bl[nh * 2 + 0][0] = t4[0]; bl[nh * 2 + 0][1] = t4[2];
                bl[nh * 2 + 1][0] = t4[1]; bl[nh * 2 + 1][1] = t4[3];
            }

#pragma unroll
            for (int mf = 0; mf < 4; ++mf)
#pragma unroll
                for (int nf = 0; nf < 4; ++nf) {
                    mma16816(acc[mf][nf], a[mf], bh[nf]);
                    mma16816(acc[mf][nf], a[mf], bl[nf]);
                }

#pragma unroll
            for (int mf = 0; mf < 4; ++mf)
                ldmx4(a[mf], st + 1 * L_AB + arow + mf * 16 * L_STRIDE);
#pragma unroll
            for (int mf = 0; mf < 4; ++mf)
#pragma unroll
                for (int nf = 0; nf < 4; ++nf)
                    mma16816(acc[mf][nf], a[mf], bh[nf]);
        }
        __syncthreads();
    }

#pragma unroll
    for (int mf = 0; mf < 4; ++mf) {
        const int mbase = m0 + wm * 64 + mf * 16;
        const int m1 = mbase + (lane >> 2);
        const int m2 = m1 + 8;
        const size_t r1 = (PERM ? (size_t)((m1 & 7) * SEQ + (m1 >> 3)) : (size_t)m1) * Ntot;
        const size_t r2 = (PERM ? (size_t)((m2 & 7) * SEQ + (m2 >> 3)) : (size_t)m2) * Ntot;
#pragma unroll
        for (int nf = 0; nf < 4; ++nf) {
            const int n = n0 + wn * 32 + nf * 8 + (lane & 3) * 2;
            const float b0 = bias[n], b1 = bias[n + 1];
            float2 o1 = {acc[mf][nf][0] + b0, acc[mf][nf][1] + b1};
            float2 o2 = {acc[mf][nf][2] + b0, acc[mf][nf][3] + b1};
            *(float2*)(out + r1 + n) = o1;
            *(float2*)(out + r2 + n) = o2;
        }
    }
}

// ---------------- launch ----------------
extern "C" void kernel_launch(void* const* d_in, const int* in_sizes, int n_in,
                              void* d_out, int out_size) {
    const int*   ids_raw  = (const int*)d_in[0];
    const float* W_out    = (const float*)d_in[1];       // [H][V]
    const float* b_out    = (const float*)d_in[2];       // [V]
    const float* Wx       = (const float*)d_in[3];       // [H][4H]
    const float* Wh       = (const float*)d_in[4];       // [H][4H]
    const float* b_lstm   = (const float*)d_in[5];       // [4H]
    float* out            = (float*)d_out;               // [B][S][V]

    void *p_xg, *p_hshi, *p_hslo, *p_wthi, *p_wtlo, *p_wxhi, *p_wxlo;
    cudaGetSymbolAddress(&p_xg,   g_xg);
    cudaGetSymbolAddress(&p_hshi, g_hs_hi);
    cudaGetSymbolAddress(&p_hslo, g_hs_lo);
    cudaGetSymbolAddress(&p_wthi, g_WT_hi);
    cudaGetSymbolAddress(&p_wtlo, g_WT_lo);
    cudaGetSymbolAddress(&p_wxhi, g_WxT_hi);
    cudaGetSymbolAddress(&p_wxlo, g_WxT_lo);

    cudaFuncSetAttribute(lstm_persistent_kernel,
                         cudaFuncAttributeMaxDynamicSharedMemorySize, LP_SMEM_BYTES);
    cudaFuncSetAttribute(mma_gemm_kernel<0>,
                         cudaFuncAttributeMaxDynamicSharedMemorySize, L_SMEM);
    cudaFuncSetAttribute(mma_gemm_kernel<1>,
                         cudaFuncAttributeMaxDynamicSharedMemorySize, L_SMEM);

    // 0) init; decode ids; transpose Wh; split W_out and Wx
    init_state_kernel<<<(2 * BATCH * HIDDEN + 255) / 256, 256>>>();
    decode_ids_kernel<<<(MROWS + 255) / 256, 256>>>(ids_raw);
    {
        dim3 tg(HIDDEN / 32, G4 / 32);
        transpose_wh_kernel<<<tg, dim3(32, 8)>>>(Wh);
    }
    transpose_split_kernel<<<dim3(VOCAB / 32, HIDDEN / 32), dim3(32, 8)>>>(
        W_out, (__nv_bfloat16*)p_wthi, (__nv_bfloat16*)p_wtlo, VOCAB);
    transpose_split_kernel<<<dim3(G4 / 32, HIDDEN / 32), dim3(32, 8)>>>(
        Wx, (__nv_bfloat16*)p_wxhi, (__nv_bfloat16*)p_wxlo, G4);

    // 1) bf16 embedding gather into g_hs_hi/lo
    gather_emb_bf16_kernel<<<MROWS, 128>>>();

    // 2) x_gates = emb @ Wx + b_lstm (fused 3-product HMMA)
    mma_gemm_kernel<0><<<dim3(MROWS / 128, G4 / 128), 256, L_SMEM>>>(
        (const __nv_bfloat16*)p_hshi, (const __nv_bfloat16*)p_hslo,
        (const __nv_bfloat16*)p_wxhi, (const __nv_bfloat16*)p_wxlo,
        b_lstm, (float*)p_xg, G4);

    // 3) recurrence: persistent FFMA2 kernel, 512 steps
    lstm_persistent_kernel<<<LP_BLOCKS, 256, LP_SMEM_BYTES>>>();

    // 4) split hs to bf16 hi/lo
    split_hs_kernel<<<(MROWS * HIDDEN / 4) / 256, 256>>>();

    // 5) logits = hs @ W_out + b_out (fused 3-product HMMA, (b,s) permute)
    mma_gemm_kernel<1><<<dim3(MROWS / 128, VOCAB / 128), 256, L_SMEM>>>(
        (const __nv_bfloat16*)p_hshi, (const __nv_bfloat16*)p_hslo,
        (const __nv_bfloat16*)p_wthi, (const __nv_bfloat16*)p_wtlo,
        b_out, out, VOCAB);
}